// round 14
// baseline (speedup 1.0000x reference)
#include <cuda_runtime.h>
#include <cstdint>
#include <math.h>

// Problem constants: B=4, C=256, H=W=64 -> N=4096, num_heads=1, d=256
#define NB    4
#define NC    256
#define NN    4096
#define NGRP  32

static __device__ float g_xn[NB * NC * NN];
static __device__ float g_q [NB * NC * NN];   // [b][c][i], q pre-scaled by d^-0.5
static __device__ float g_k [NB * NC * NN];
static __device__ float g_v [NB * NC * NN];
static __device__ float g_o [NB * NC * NN];
static __device__ float g_S [(size_t)NB * NN * NN];   // 256 MB scores / probs

static constexpr size_t STR_CN = (size_t)NC * NN;     // 1048576
static constexpr size_t STR_NN = (size_t)NN * NN;     // 16777216

// smem geometry for the double-buffered GEMM
static constexpr int AS_W = 132;                      // 128 + 4 pad (floats)
static constexpr int BS_W = 68;                       // 64 + 4 pad
static constexpr int AS_TILE = 32 * AS_W;             // floats per A buffer
static constexpr int BS_TILE = 32 * BS_W;
static constexpr int GEMM_SMEM = (2 * AS_TILE + 2 * BS_TILE) * 4;   // 51200 B

// ===========================================================================
// GroupNorm (round-1 proven)
// ===========================================================================
__global__ void __launch_bounds__(256) gn_kernel(const float* __restrict__ x,
                                                 const float* __restrict__ w,
                                                 const float* __restrict__ b) {
    int batch = blockIdx.x >> 5;
    int grp   = blockIdx.x & 31;
    const float* xp = x    + ((size_t)batch * NC + grp * 8) * NN;
    float*       op = g_xn + ((size_t)batch * NC + grp * 8) * NN;
    int tid = threadIdx.x;

    float s = 0.f, s2 = 0.f;
    #pragma unroll 4
    for (int i = tid; i < 8192; i += 256) {
        float4 t = reinterpret_cast<const float4*>(xp)[i];
        s  += t.x + t.y + t.z + t.w;
        s2 += t.x * t.x + t.y * t.y + t.z * t.z + t.w * t.w;
    }
    __shared__ float rs[8], rs2[8];
    __shared__ float sh_mean, sh_rstd;
    int lane = tid & 31, wid = tid >> 5;
    #pragma unroll
    for (int o = 16; o; o >>= 1) {
        s  += __shfl_xor_sync(0xffffffffu, s,  o);
        s2 += __shfl_xor_sync(0xffffffffu, s2, o);
    }
    if (lane == 0) { rs[wid] = s; rs2[wid] = s2; }
    __syncthreads();
    if (tid == 0) {
        float ts = 0.f, ts2 = 0.f;
        #pragma unroll
        for (int i = 0; i < 8; i++) { ts += rs[i]; ts2 += rs2[i]; }
        float mean = ts * (1.0f / 32768.0f);
        float var  = ts2 * (1.0f / 32768.0f) - mean * mean;
        sh_mean = mean;
        sh_rstd = rsqrtf(var + 1e-5f);
    }
    __syncthreads();
    float mean = sh_mean, rstd = sh_rstd;

    #pragma unroll 4
    for (int i = tid; i < 8192; i += 256) {
        int c = grp * 8 + (i >> 10);
        float sc = rstd * w[c];
        float shf = b[c] - mean * sc;
        float4 t = reinterpret_cast<const float4*>(xp)[i];
        t.x = t.x * sc + shf; t.y = t.y * sc + shf;
        t.z = t.z * sc + shf; t.w = t.w * sc + shf;
        reinterpret_cast<float4*>(op)[i] = t;
    }
}

// ===========================================================================
// Staging helpers (global -> regs -> smem), layouts identical to round-1.
// ===========================================================================
template <bool A_T, int LDA>
__device__ __forceinline__ void stageA(float4 (&pa)[4], const float* __restrict__ A,
                                       int m0, int k0, int tid) {
    if constexpr (A_T) {
        int m = tid >> 3, kq = tid & 7;
        #pragma unroll
        for (int it = 0; it < 4; ++it)
            pa[it] = *reinterpret_cast<const float4*>(&A[(size_t)(m0 + m + 32 * it) * LDA + k0 + kq * 4]);
    } else {
        int kk = tid >> 5, m4 = tid & 31;
        #pragma unroll
        for (int it = 0; it < 4; ++it)
            pa[it] = *reinterpret_cast<const float4*>(&A[(size_t)(k0 + kk + 8 * it) * LDA + m0 + m4 * 4]);
    }
}
template <bool A_T>
__device__ __forceinline__ void commitA(float* As, const float4 (&pa)[4], int tid) {
    if constexpr (A_T) {
        int m = tid >> 3, kq = tid & 7;
        #pragma unroll
        for (int it = 0; it < 4; ++it) {
            As[(kq * 4 + 0) * AS_W + m + 32 * it] = pa[it].x;
            As[(kq * 4 + 1) * AS_W + m + 32 * it] = pa[it].y;
            As[(kq * 4 + 2) * AS_W + m + 32 * it] = pa[it].z;
            As[(kq * 4 + 3) * AS_W + m + 32 * it] = pa[it].w;
        }
    } else {
        int kk = tid >> 5, m4 = tid & 31;
        #pragma unroll
        for (int it = 0; it < 4; ++it)
            *reinterpret_cast<float4*>(&As[(kk + 8 * it) * AS_W + m4 * 4]) = pa[it];
    }
}
template <bool B_T, int LDB>
__device__ __forceinline__ void stageB(float4 (&pb)[2], const float* __restrict__ B,
                                       int n0, int k0, int tid) {
    if constexpr (B_T) {
        int n = tid >> 3, kq = tid & 7;
        #pragma unroll
        for (int it = 0; it < 2; ++it)
            pb[it] = *reinterpret_cast<const float4*>(&B[(size_t)(n0 + n + 32 * it) * LDB + k0 + kq * 4]);
    } else {
        int kk = tid >> 4, n4 = tid & 15;
        #pragma unroll
        for (int it = 0; it < 2; ++it)
            pb[it] = *reinterpret_cast<const float4*>(&B[(size_t)(k0 + kk + 16 * it) * LDB + n0 + n4 * 4]);
    }
}
template <bool B_T>
__device__ __forceinline__ void commitB(float* Bs, const float4 (&pb)[2], int tid) {
    if constexpr (B_T) {
        int n = tid >> 3, kq = tid & 7;
        #pragma unroll
        for (int it = 0; it < 2; ++it) {
            Bs[(kq * 4 + 0) * BS_W + n + 32 * it] = pb[it].x;
            Bs[(kq * 4 + 1) * BS_W + n + 32 * it] = pb[it].y;
            Bs[(kq * 4 + 2) * BS_W + n + 32 * it] = pb[it].z;
            Bs[(kq * 4 + 3) * BS_W + n + 32 * it] = pb[it].w;
        }
    } else {
        int kk = tid >> 4, n4 = tid & 15;
        #pragma unroll
        for (int it = 0; it < 2; ++it)
            *reinterpret_cast<float4*>(&Bs[(kk + 16 * it) * BS_W + n4 * 4]) = pb[it];
    }
}

// ===========================================================================
// Unified FFMA2 GEMM (all four ops). Row-pair f32x2 inner loop (bitwise-
// identical to scalar fp32), double-buffered smem (ONE barrier per k-tile),
// A operands loaded directly as u64 pairs (zero packing movs on the A side).
// ===========================================================================
#define OP_QKV  0
#define OP_S    1
#define OP_AV   2
#define OP_PROJ 3

template <int OP>
__global__ void __launch_bounds__(256) gemm2_kernel(const float* __restrict__ extA,
                                                    const float* __restrict__ bias,
                                                    const float* __restrict__ resid,
                                                    float* __restrict__ extOut) {
    constexpr int BM = 128, BN = 64, BK = 32;
    constexpr int K   = (OP == OP_AV) ? 4096 : 256;
    constexpr bool A_T = (OP == OP_QKV || OP == OP_AV || OP == OP_PROJ);
    constexpr bool B_T = (OP == OP_AV);
    constexpr int LDA = (OP == OP_QKV || OP == OP_PROJ) ? 256 : 4096;
    constexpr int LDB = 4096;

    extern __shared__ float smem[];
    float* AsBuf[2] = { smem, smem + AS_TILE };
    float* BsBuf[2] = { smem + 2 * AS_TILE, smem + 2 * AS_TILE + BS_TILE };

    size_t bz = blockIdx.z;
    const float* A;
    const float* B;
    if constexpr (OP == OP_QKV)      { A = extA;              B = g_xn + bz * STR_CN; }
    else if constexpr (OP == OP_S)   { A = g_q + bz * STR_CN; B = g_k  + bz * STR_CN; }
    else if constexpr (OP == OP_AV)  { A = g_v + bz * STR_CN; B = g_S  + bz * STR_NN; }
    else                             { A = extA;              B = g_o  + bz * STR_CN; }

    int m0 = blockIdx.y * BM;
    int n0 = blockIdx.x * BN;
    int tid = threadIdx.x;
    int tr = tid >> 4;
    int tc = tid & 15;

    // acc2[ip][j]: lane0 = row tr*8 + 2*ip, lane1 = row tr*8 + 2*ip + 1, col j
    unsigned long long acc2[4][4];
    #pragma unroll
    for (int i = 0; i < 4; i++)
        #pragma unroll
        for (int j = 0; j < 4; j++) acc2[i][j] = 0ULL;

    // Prologue: tile 0 into buffer 0
    {
        float4 pa[4]; float4 pb[2];
        stageA<A_T, LDA>(pa, A, m0, 0, tid);
        stageB<B_T, LDB>(pb, B, n0, 0, tid);
        commitA<A_T>(AsBuf[0], pa, tid);
        commitB<B_T>(BsBuf[0], pb, tid);
    }
    __syncthreads();

    int buf = 0;
    #pragma unroll 1
    for (int k0 = 0; k0 < K; k0 += BK) {
        float4 pa[4]; float4 pb[2];
        bool has_next = (k0 + BK) < K;
        if (has_next) {                    // LDG issued before compute: hidden
            stageA<A_T, LDA>(pa, A, m0, k0 + BK, tid);
            stageB<B_T, LDB>(pb, B, n0, k0 + BK, tid);
        }

        const float* Asb = AsBuf[buf];
        const float* Bsb = BsBuf[buf];
        #pragma unroll
        for (int kk = 0; kk < BK; ++kk) {
            // A rows tr*8..+7 at this k: two LDS.128 that ARE the u64 pairs
            ulonglong2 ua = *reinterpret_cast<const ulonglong2*>(&Asb[kk * AS_W + tr * 8]);
            ulonglong2 ub = *reinterpret_cast<const ulonglong2*>(&Asb[kk * AS_W + tr * 8 + 4]);
            float4 b0 = *reinterpret_cast<const float4*>(&Bsb[kk * BS_W + tc * 4]);
            unsigned long long bd[4];
            asm("mov.b64 %0, {%1, %1};" : "=l"(bd[0]) : "f"(b0.x));
            asm("mov.b64 %0, {%1, %1};" : "=l"(bd[1]) : "f"(b0.y));
            asm("mov.b64 %0, {%1, %1};" : "=l"(bd[2]) : "f"(b0.z));
            asm("mov.b64 %0, {%1, %1};" : "=l"(bd[3]) : "f"(b0.w));
            #pragma unroll
            for (int j = 0; j < 4; j++) {
                asm("fma.rn.f32x2 %0, %1, %2, %0;" : "+l"(acc2[0][j]) : "l"(ua.x), "l"(bd[j]));
                asm("fma.rn.f32x2 %0, %1, %2, %0;" : "+l"(acc2[1][j]) : "l"(ua.y), "l"(bd[j]));
                asm("fma.rn.f32x2 %0, %1, %2, %0;" : "+l"(acc2[2][j]) : "l"(ub.x), "l"(bd[j]));
                asm("fma.rn.f32x2 %0, %1, %2, %0;" : "+l"(acc2[3][j]) : "l"(ub.y), "l"(bd[j]));
            }
        }

        if (has_next) {
            // commit into the OTHER buffer: no wait on co-resident readers
            commitA<A_T>(AsBuf[buf ^ 1], pa, tid);
            commitB<B_T>(BsBuf[buf ^ 1], pb, tid);
            buf ^= 1;
            __syncthreads();               // single barrier per k-tile
        }
    }

    // Unpack packed accumulators into the round-1 acc[8][4] shape
    float acc[8][4];
    #pragma unroll
    for (int ip = 0; ip < 4; ip++)
        #pragma unroll
        for (int j = 0; j < 4; j++)
            asm("mov.b64 {%0, %1}, %2;"
                : "=f"(acc[2 * ip][j]), "=f"(acc[2 * ip + 1][j]) : "l"(acc2[ip][j]));

    // ---- round-1 proven epilogues ----
    int nbase = n0 + tc * 4;
    #pragma unroll
    for (int i = 0; i < 8; i++) {
        int m = m0 + tr * 8 + i;
        float4 r = make_float4(acc[i][0], acc[i][1], acc[i][2], acc[i][3]);
        if constexpr (OP == OP_QKV) {
            float bv = bias[m];
            r.x += bv; r.y += bv; r.z += bv; r.w += bv;
            size_t off = bz * STR_CN + (size_t)(m & 255) * NN + nbase;
            if (m < 256) {
                r.x *= 0.0625f; r.y *= 0.0625f; r.z *= 0.0625f; r.w *= 0.0625f;
                *reinterpret_cast<float4*>(&g_q[off]) = r;
            } else if (m < 512) {
                *reinterpret_cast<float4*>(&g_k[off]) = r;
            } else {
                *reinterpret_cast<float4*>(&g_v[off]) = r;
            }
        } else if constexpr (OP == OP_S) {
            *reinterpret_cast<float4*>(&g_S[bz * STR_NN + (size_t)m * NN + nbase]) = r;
        } else if constexpr (OP == OP_AV) {
            *reinterpret_cast<float4*>(&g_o[bz * STR_CN + (size_t)m * NN + nbase]) = r;
        } else {
            float bv = bias[m];
            size_t off = bz * STR_CN + (size_t)m * NN + nbase;
            float4 xr = *reinterpret_cast<const float4*>(&resid[off]);
            r.x += bv + xr.x; r.y += bv + xr.y; r.z += bv + xr.z; r.w += bv + xr.w;
            *reinterpret_cast<float4*>(&extOut[off]) = r;
        }
    }
}

// ===========================================================================
// Softmax (round-1 proven), in place on g_S
// ===========================================================================
__global__ void __launch_bounds__(256) softmax_kernel() {
    size_t row = blockIdx.x;
    float* p = g_S + row * NN;
    int tid = threadIdx.x;
    int lane = tid & 31, wid = tid >> 5;
    __shared__ float red[8];
    __shared__ float sh_bcast;

    float4 v[4];
    float mx = -INFINITY;
    #pragma unroll
    for (int i = 0; i < 4; i++) {
        v[i] = reinterpret_cast<float4*>(p)[tid + i * 256];
        mx = fmaxf(mx, fmaxf(fmaxf(v[i].x, v[i].y), fmaxf(v[i].z, v[i].w)));
    }
    #pragma unroll
    for (int o = 16; o; o >>= 1) mx = fmaxf(mx, __shfl_xor_sync(0xffffffffu, mx, o));
    if (lane == 0) red[wid] = mx;
    __syncthreads();
    if (tid == 0) {
        float m = red[0];
        #pragma unroll
        for (int i = 1; i < 8; i++) m = fmaxf(m, red[i]);
        sh_bcast = m;
    }
    __syncthreads();
    mx = sh_bcast;
    __syncthreads();

    float sum = 0.f;
    #pragma unroll
    for (int i = 0; i < 4; i++) {
        v[i].x = __expf(v[i].x - mx); v[i].y = __expf(v[i].y - mx);
        v[i].z = __expf(v[i].z - mx); v[i].w = __expf(v[i].w - mx);
        sum += v[i].x + v[i].y + v[i].z + v[i].w;
    }
    #pragma unroll
    for (int o = 16; o; o >>= 1) sum += __shfl_xor_sync(0xffffffffu, sum, o);
    if (lane == 0) red[wid] = sum;
    __syncthreads();
    if (tid == 0) {
        float s = 0.f;
        #pragma unroll
        for (int i = 0; i < 8; i++) s += red[i];
        sh_bcast = 1.0f / s;
    }
    __syncthreads();
    float inv = sh_bcast;

    #pragma unroll
    for (int i = 0; i < 4; i++) {
        v[i].x *= inv; v[i].y *= inv; v[i].z *= inv; v[i].w *= inv;
        reinterpret_cast<float4*>(p)[tid + i * 256] = v[i];
    }
}

// ===========================================================================
extern "C" void kernel_launch(void* const* d_in, const int* in_sizes, int n_in,
                              void* d_out, int out_size) {
    const float* x      = (const float*)d_in[0];
    const float* norm_w = (const float*)d_in[1];
    const float* norm_b = (const float*)d_in[2];
    const float* qkv_w  = (const float*)d_in[3];
    const float* qkv_b  = (const float*)d_in[4];
    const float* proj_w = (const float*)d_in[5];
    const float* proj_b = (const float*)d_in[6];
    float* out = (float*)d_out;

    cudaFuncSetAttribute(gemm2_kernel<OP_QKV>,  cudaFuncAttributeMaxDynamicSharedMemorySize, GEMM_SMEM);
    cudaFuncSetAttribute(gemm2_kernel<OP_S>,    cudaFuncAttributeMaxDynamicSharedMemorySize, GEMM_SMEM);
    cudaFuncSetAttribute(gemm2_kernel<OP_AV>,   cudaFuncAttributeMaxDynamicSharedMemorySize, GEMM_SMEM);
    cudaFuncSetAttribute(gemm2_kernel<OP_PROJ>, cudaFuncAttributeMaxDynamicSharedMemorySize, GEMM_SMEM);

    // 1. GroupNorm -> g_xn
    gn_kernel<<<NB * NGRP, 256>>>(x, norm_w, norm_b);

    // 2. QKV GEMM (f32x2) -> g_q (scaled), g_k, g_v
    gemm2_kernel<OP_QKV><<<dim3(NN / 64, 768 / 128, NB), 256, GEMM_SMEM>>>(qkv_w, qkv_b, nullptr, nullptr);

    // 3. S = Q^T K (f32x2)
    gemm2_kernel<OP_S><<<dim3(NN / 64, NN / 128, NB), 256, GEMM_SMEM>>>(nullptr, nullptr, nullptr, nullptr);

    // 4. softmax (fp32, proven)
    softmax_kernel<<<NB * NN, 256>>>();

    // 5. O = V P^T (f32x2)
    gemm2_kernel<OP_AV><<<dim3(NN / 64, NC / 128, NB), 256, GEMM_SMEM>>>(nullptr, nullptr, nullptr, nullptr);

    // 6. proj + bias + residual (f32x2)
    gemm2_kernel<OP_PROJ><<<dim3(NN / 64, NC / 128, NB), 256, GEMM_SMEM>>>(proj_w, proj_b, x, out);
}

// round 15
// speedup vs baseline: 1.3225x; 1.3225x over previous
#include <cuda_runtime.h>
#include <cstdint>
#include <math.h>

// Problem constants: B=4, C=256, H=W=64 -> N=4096, num_heads=1, d=256
#define NB    4
#define NC    256
#define NN    4096
#define NGRP  32

static __device__ float g_xn[NB * NC * NN];
static __device__ float g_q [NB * NC * NN];   // [b][c][i], q pre-scaled by d^-0.5
static __device__ float g_k [NB * NC * NN];
static __device__ float g_v [NB * NC * NN];
static __device__ float g_o [NB * NC * NN];
static __device__ float g_S [(size_t)NB * NN * NN];   // 256 MB scores / probs

static constexpr size_t STR_CN = (size_t)NC * NN;     // 1048576
static constexpr size_t STR_NN = (size_t)NN * NN;     // 16777216

// ===========================================================================
// GroupNorm (round-1 proven)
// ===========================================================================
__global__ void __launch_bounds__(256) gn_kernel(const float* __restrict__ x,
                                                 const float* __restrict__ w,
                                                 const float* __restrict__ b) {
    int batch = blockIdx.x >> 5;
    int grp   = blockIdx.x & 31;
    const float* xp = x    + ((size_t)batch * NC + grp * 8) * NN;
    float*       op = g_xn + ((size_t)batch * NC + grp * 8) * NN;
    int tid = threadIdx.x;

    float s = 0.f, s2 = 0.f;
    #pragma unroll 4
    for (int i = tid; i < 8192; i += 256) {
        float4 t = reinterpret_cast<const float4*>(xp)[i];
        s  += t.x + t.y + t.z + t.w;
        s2 += t.x * t.x + t.y * t.y + t.z * t.z + t.w * t.w;
    }
    __shared__ float rs[8], rs2[8];
    __shared__ float sh_mean, sh_rstd;
    int lane = tid & 31, wid = tid >> 5;
    #pragma unroll
    for (int o = 16; o; o >>= 1) {
        s  += __shfl_xor_sync(0xffffffffu, s,  o);
        s2 += __shfl_xor_sync(0xffffffffu, s2, o);
    }
    if (lane == 0) { rs[wid] = s; rs2[wid] = s2; }
    __syncthreads();
    if (tid == 0) {
        float ts = 0.f, ts2 = 0.f;
        #pragma unroll
        for (int i = 0; i < 8; i++) { ts += rs[i]; ts2 += rs2[i]; }
        float mean = ts * (1.0f / 32768.0f);
        float var  = ts2 * (1.0f / 32768.0f) - mean * mean;
        sh_mean = mean;
        sh_rstd = rsqrtf(var + 1e-5f);
    }
    __syncthreads();
    float mean = sh_mean, rstd = sh_rstd;

    #pragma unroll 4
    for (int i = tid; i < 8192; i += 256) {
        int c = grp * 8 + (i >> 10);
        float sc = rstd * w[c];
        float shf = b[c] - mean * sc;
        float4 t = reinterpret_cast<const float4*>(xp)[i];
        t.x = t.x * sc + shf; t.y = t.y * sc + shf;
        t.z = t.z * sc + shf; t.w = t.w * sc + shf;
        reinterpret_cast<float4*>(op)[i] = t;
    }
}

// ===========================================================================
// Staging helpers (global -> regs -> smem), layouts identical to round-1.
// ===========================================================================
template <bool A_T, int LDA>
__device__ __forceinline__ void stageA(float4 (&pa)[4], const float* __restrict__ A,
                                       int m0, int k0, int tid) {
    if constexpr (A_T) {
        int m = tid >> 3, kq = tid & 7;
        #pragma unroll
        for (int it = 0; it < 4; ++it)
            pa[it] = *reinterpret_cast<const float4*>(&A[(size_t)(m0 + m + 32 * it) * LDA + k0 + kq * 4]);
    } else {
        int kk = tid >> 5, m4 = tid & 31;
        #pragma unroll
        for (int it = 0; it < 4; ++it)
            pa[it] = *reinterpret_cast<const float4*>(&A[(size_t)(k0 + kk + 8 * it) * LDA + m0 + m4 * 4]);
    }
}
template <bool A_T>
__device__ __forceinline__ void commitA(float (*As)[132], const float4 (&pa)[4], int tid) {
    if constexpr (A_T) {
        int m = tid >> 3, kq = tid & 7;
        #pragma unroll
        for (int it = 0; it < 4; ++it) {
            As[kq * 4 + 0][m + 32 * it] = pa[it].x;
            As[kq * 4 + 1][m + 32 * it] = pa[it].y;
            As[kq * 4 + 2][m + 32 * it] = pa[it].z;
            As[kq * 4 + 3][m + 32 * it] = pa[it].w;
        }
    } else {
        int kk = tid >> 5, m4 = tid & 31;
        #pragma unroll
        for (int it = 0; it < 4; ++it)
            *reinterpret_cast<float4*>(&As[kk + 8 * it][m4 * 4]) = pa[it];
    }
}
template <bool B_T, int LDB>
__device__ __forceinline__ void stageB(float4 (&pb)[2], const float* __restrict__ B,
                                       int n0, int k0, int tid) {
    if constexpr (B_T) {
        int n = tid >> 3, kq = tid & 7;
        #pragma unroll
        for (int it = 0; it < 2; ++it)
            pb[it] = *reinterpret_cast<const float4*>(&B[(size_t)(n0 + n + 32 * it) * LDB + k0 + kq * 4]);
    } else {
        int kk = tid >> 4, n4 = tid & 15;
        #pragma unroll
        for (int it = 0; it < 2; ++it)
            pb[it] = *reinterpret_cast<const float4*>(&B[(size_t)(k0 + kk + 16 * it) * LDB + n0 + n4 * 4]);
    }
}
template <bool B_T>
__device__ __forceinline__ void commitB(float (*Bs)[68], const float4 (&pb)[2], int tid) {
    if constexpr (B_T) {
        int n = tid >> 3, kq = tid & 7;
        #pragma unroll
        for (int it = 0; it < 2; ++it) {
            Bs[kq * 4 + 0][n + 32 * it] = pb[it].x;
            Bs[kq * 4 + 1][n + 32 * it] = pb[it].y;
            Bs[kq * 4 + 2][n + 32 * it] = pb[it].z;
            Bs[kq * 4 + 3][n + 32 * it] = pb[it].w;
        }
    } else {
        int kk = tid >> 4, n4 = tid & 15;
        #pragma unroll
        for (int it = 0; it < 2; ++it)
            *reinterpret_cast<float4*>(&Bs[kk + 16 * it][n4 * 4]) = pb[it];
    }
}

// ===========================================================================
// Unified FFMA2 GEMM (all four ops). R13 structure exactly (static smem,
// register-staged prefetch, two barriers per k-tile); ONLY change: A operands
// are loaded from smem directly as ulonglong2 (the LDS.128 register quad IS
// the two f32x2 operand pairs) -> the 4 a-side mov.b64 per kk are gone.
// Row-pair FFMA2 lanes: bitwise-identical results to the scalar fp32 kernel.
// ===========================================================================
#define OP_QKV  0
#define OP_S    1
#define OP_AV   2
#define OP_PROJ 3

template <int OP>
__global__ void __launch_bounds__(256) gemm2_kernel(const float* __restrict__ extA,
                                                    const float* __restrict__ bias,
                                                    const float* __restrict__ resid,
                                                    float* __restrict__ extOut) {
    constexpr int BM = 128, BN = 64, BK = 32;
    constexpr int K   = (OP == OP_AV) ? 4096 : 256;
    constexpr bool A_T = (OP == OP_QKV || OP == OP_AV || OP == OP_PROJ);
    constexpr bool B_T = (OP == OP_AV);
    constexpr int LDA = (OP == OP_QKV || OP == OP_PROJ) ? 256 : 4096;
    constexpr int LDB = 4096;

    __shared__ float As[BK][BM + 4];
    __shared__ float Bs[BK][BN + 4];

    size_t bz = blockIdx.z;
    const float* A;
    const float* B;
    if constexpr (OP == OP_QKV)      { A = extA;              B = g_xn + bz * STR_CN; }
    else if constexpr (OP == OP_S)   { A = g_q + bz * STR_CN; B = g_k  + bz * STR_CN; }
    else if constexpr (OP == OP_AV)  { A = g_v + bz * STR_CN; B = g_S  + bz * STR_NN; }
    else                             { A = extA;              B = g_o  + bz * STR_CN; }

    int m0 = blockIdx.y * BM;
    int n0 = blockIdx.x * BN;
    int tid = threadIdx.x;
    int tr = tid >> 4;
    int tc = tid & 15;

    // acc2[ip][j]: lane0 = row tr*8 + 2*ip, lane1 = row tr*8 + 2*ip + 1, col j
    unsigned long long acc2[4][4];
    #pragma unroll
    for (int i = 0; i < 4; i++)
        #pragma unroll
        for (int j = 0; j < 4; j++) acc2[i][j] = 0ULL;

    // Prologue: tile 0 straight to smem
    {
        float4 pa[4]; float4 pb[2];
        stageA<A_T, LDA>(pa, A, m0, 0, tid);
        stageB<B_T, LDB>(pb, B, n0, 0, tid);
        commitA<A_T>(As, pa, tid);
        commitB<B_T>(Bs, pb, tid);
    }
    __syncthreads();

    #pragma unroll 1
    for (int k0 = 0; k0 < K; k0 += BK) {
        float4 pa[4]; float4 pb[2];
        bool has_next = (k0 + BK) < K;
        if (has_next) {                    // LDG issued before compute: hidden
            stageA<A_T, LDA>(pa, A, m0, k0 + BK, tid);
            stageB<B_T, LDB>(pb, B, n0, k0 + BK, tid);
        }

        #pragma unroll
        for (int kk = 0; kk < BK; ++kk) {
            // A rows tr*8..+7 at this k: the two LDS.128 ARE the u64 pairs
            ulonglong2 ua = *reinterpret_cast<const ulonglong2*>(&As[kk][tr * 8]);
            ulonglong2 ub = *reinterpret_cast<const ulonglong2*>(&As[kk][tr * 8 + 4]);
            float4 b0 = *reinterpret_cast<const float4*>(&Bs[kk][tc * 4]);
            unsigned long long bd[4];
            asm("mov.b64 %0, {%1, %1};" : "=l"(bd[0]) : "f"(b0.x));
            asm("mov.b64 %0, {%1, %1};" : "=l"(bd[1]) : "f"(b0.y));
            asm("mov.b64 %0, {%1, %1};" : "=l"(bd[2]) : "f"(b0.z));
            asm("mov.b64 %0, {%1, %1};" : "=l"(bd[3]) : "f"(b0.w));
            #pragma unroll
            for (int j = 0; j < 4; j++) {
                asm("fma.rn.f32x2 %0, %1, %2, %0;" : "+l"(acc2[0][j]) : "l"(ua.x), "l"(bd[j]));
                asm("fma.rn.f32x2 %0, %1, %2, %0;" : "+l"(acc2[1][j]) : "l"(ua.y), "l"(bd[j]));
                asm("fma.rn.f32x2 %0, %1, %2, %0;" : "+l"(acc2[2][j]) : "l"(ub.x), "l"(bd[j]));
                asm("fma.rn.f32x2 %0, %1, %2, %0;" : "+l"(acc2[3][j]) : "l"(ub.y), "l"(bd[j]));
            }
        }

        if (has_next) {
            __syncthreads();               // all reads of current tile done
            commitA<A_T>(As, pa, tid);
            commitB<B_T>(Bs, pb, tid);
            __syncthreads();               // new tile visible
        }
    }

    // Unpack packed accumulators into the round-1 acc[8][4] shape
    float acc[8][4];
    #pragma unroll
    for (int ip = 0; ip < 4; ip++)
        #pragma unroll
        for (int j = 0; j < 4; j++)
            asm("mov.b64 {%0, %1}, %2;"
                : "=f"(acc[2 * ip][j]), "=f"(acc[2 * ip + 1][j]) : "l"(acc2[ip][j]));

    // ---- round-1 proven epilogues ----
    int nbase = n0 + tc * 4;
    #pragma unroll
    for (int i = 0; i < 8; i++) {
        int m = m0 + tr * 8 + i;
        float4 r = make_float4(acc[i][0], acc[i][1], acc[i][2], acc[i][3]);
        if constexpr (OP == OP_QKV) {
            float bv = bias[m];
            r.x += bv; r.y += bv; r.z += bv; r.w += bv;
            size_t off = bz * STR_CN + (size_t)(m & 255) * NN + nbase;
            if (m < 256) {
                r.x *= 0.0625f; r.y *= 0.0625f; r.z *= 0.0625f; r.w *= 0.0625f;
                *reinterpret_cast<float4*>(&g_q[off]) = r;
            } else if (m < 512) {
                *reinterpret_cast<float4*>(&g_k[off]) = r;
            } else {
                *reinterpret_cast<float4*>(&g_v[off]) = r;
            }
        } else if constexpr (OP == OP_S) {
            *reinterpret_cast<float4*>(&g_S[bz * STR_NN + (size_t)m * NN + nbase]) = r;
        } else if constexpr (OP == OP_AV) {
            *reinterpret_cast<float4*>(&g_o[bz * STR_CN + (size_t)m * NN + nbase]) = r;
        } else {
            float bv = bias[m];
            size_t off = bz * STR_CN + (size_t)m * NN + nbase;
            float4 xr = *reinterpret_cast<const float4*>(&resid[off]);
            r.x += bv + xr.x; r.y += bv + xr.y; r.z += bv + xr.z; r.w += bv + xr.w;
            *reinterpret_cast<float4*>(&extOut[off]) = r;
        }
    }
}

// ===========================================================================
// Softmax (round-1 proven), in place on g_S
// ===========================================================================
__global__ void __launch_bounds__(256) softmax_kernel() {
    size_t row = blockIdx.x;
    float* p = g_S + row * NN;
    int tid = threadIdx.x;
    int lane = tid & 31, wid = tid >> 5;
    __shared__ float red[8];
    __shared__ float sh_bcast;

    float4 v[4];
    float mx = -INFINITY;
    #pragma unroll
    for (int i = 0; i < 4; i++) {
        v[i] = reinterpret_cast<float4*>(p)[tid + i * 256];
        mx = fmaxf(mx, fmaxf(fmaxf(v[i].x, v[i].y), fmaxf(v[i].z, v[i].w)));
    }
    #pragma unroll
    for (int o = 16; o; o >>= 1) mx = fmaxf(mx, __shfl_xor_sync(0xffffffffu, mx, o));
    if (lane == 0) red[wid] = mx;
    __syncthreads();
    if (tid == 0) {
        float m = red[0];
        #pragma unroll
        for (int i = 1; i < 8; i++) m = fmaxf(m, red[i]);
        sh_bcast = m;
    }
    __syncthreads();
    mx = sh_bcast;
    __syncthreads();

    float sum = 0.f;
    #pragma unroll
    for (int i = 0; i < 4; i++) {
        v[i].x = __expf(v[i].x - mx); v[i].y = __expf(v[i].y - mx);
        v[i].z = __expf(v[i].z - mx); v[i].w = __expf(v[i].w - mx);
        sum += v[i].x + v[i].y + v[i].z + v[i].w;
    }
    #pragma unroll
    for (int o = 16; o; o >>= 1) sum += __shfl_xor_sync(0xffffffffu, sum, o);
    if (lane == 0) red[wid] = sum;
    __syncthreads();
    if (tid == 0) {
        float s = 0.f;
        #pragma unroll
        for (int i = 0; i < 8; i++) s += red[i];
        sh_bcast = 1.0f / s;
    }
    __syncthreads();
    float inv = sh_bcast;

    #pragma unroll
    for (int i = 0; i < 4; i++) {
        v[i].x *= inv; v[i].y *= inv; v[i].z *= inv; v[i].w *= inv;
        reinterpret_cast<float4*>(p)[tid + i * 256] = v[i];
    }
}

// ===========================================================================
extern "C" void kernel_launch(void* const* d_in, const int* in_sizes, int n_in,
                              void* d_out, int out_size) {
    const float* x      = (const float*)d_in[0];
    const float* norm_w = (const float*)d_in[1];
    const float* norm_b = (const float*)d_in[2];
    const float* qkv_w  = (const float*)d_in[3];
    const float* qkv_b  = (const float*)d_in[4];
    const float* proj_w = (const float*)d_in[5];
    const float* proj_b = (const float*)d_in[6];
    float* out = (float*)d_out;

    // 1. GroupNorm -> g_xn
    gn_kernel<<<NB * NGRP, 256>>>(x, norm_w, norm_b);

    // 2. QKV GEMM (f32x2) -> g_q (scaled), g_k, g_v
    gemm2_kernel<OP_QKV><<<dim3(NN / 64, 768 / 128, NB), 256>>>(qkv_w, qkv_b, nullptr, nullptr);

    // 3. S = Q^T K (f32x2)
    gemm2_kernel<OP_S><<<dim3(NN / 64, NN / 128, NB), 256>>>(nullptr, nullptr, nullptr, nullptr);

    // 4. softmax (fp32, proven)
    softmax_kernel<<<NB * NN, 256>>>();

    // 5. O = V P^T (f32x2)
    gemm2_kernel<OP_AV><<<dim3(NN / 64, NC / 128, NB), 256>>>(nullptr, nullptr, nullptr, nullptr);

    // 6. proj + bias + residual (f32x2)
    gemm2_kernel<OP_PROJ><<<dim3(NN / 64, NC / 128, NB), 256>>>(proj_w, proj_b, x, out);
}

// round 16
// speedup vs baseline: 1.3569x; 1.0260x over previous
#include <cuda_runtime.h>
#include <cstdint>
#include <math.h>

// Problem constants: B=4, C=256, H=W=64 -> N=4096, num_heads=1, d=256
#define NB    4
#define NC    256
#define NN    4096
#define NGRP  32

static __device__ float g_xn[NB * NC * NN];
static __device__ float g_q [NB * NC * NN];   // [b][c][i], q pre-scaled by d^-0.5
static __device__ float g_k [NB * NC * NN];
static __device__ float g_vT[NB * NN * NC];   // [b][j][c]  (transposed V)
static __device__ float g_o [NB * NC * NN];
static __device__ float g_S [(size_t)NB * NN * NN];   // 256 MB scores / probs

static constexpr size_t STR_CN = (size_t)NC * NN;     // 1048576
static constexpr size_t STR_NN = (size_t)NN * NN;     // 16777216

// smem geometry (double-buffered)
static constexpr int AS_W = 132;
static constexpr int BS_W = 68;
static constexpr int AS_TILE = 32 * AS_W;
static constexpr int BS_TILE = 32 * BS_W;
static constexpr int GEMM_SMEM = (2 * AS_TILE + 2 * BS_TILE) * 4;   // 51200 B

// ===========================================================================
// GroupNorm (round-1 proven)
// ===========================================================================
__global__ void __launch_bounds__(256) gn_kernel(const float* __restrict__ x,
                                                 const float* __restrict__ w,
                                                 const float* __restrict__ b) {
    int batch = blockIdx.x >> 5;
    int grp   = blockIdx.x & 31;
    const float* xp = x    + ((size_t)batch * NC + grp * 8) * NN;
    float*       op = g_xn + ((size_t)batch * NC + grp * 8) * NN;
    int tid = threadIdx.x;

    float s = 0.f, s2 = 0.f;
    #pragma unroll 4
    for (int i = tid; i < 8192; i += 256) {
        float4 t = reinterpret_cast<const float4*>(xp)[i];
        s  += t.x + t.y + t.z + t.w;
        s2 += t.x * t.x + t.y * t.y + t.z * t.z + t.w * t.w;
    }
    __shared__ float rs[8], rs2[8];
    __shared__ float sh_mean, sh_rstd;
    int lane = tid & 31, wid = tid >> 5;
    #pragma unroll
    for (int o = 16; o; o >>= 1) {
        s  += __shfl_xor_sync(0xffffffffu, s,  o);
        s2 += __shfl_xor_sync(0xffffffffu, s2, o);
    }
    if (lane == 0) { rs[wid] = s; rs2[wid] = s2; }
    __syncthreads();
    if (tid == 0) {
        float ts = 0.f, ts2 = 0.f;
        #pragma unroll
        for (int i = 0; i < 8; i++) { ts += rs[i]; ts2 += rs2[i]; }
        float mean = ts * (1.0f / 32768.0f);
        float var  = ts2 * (1.0f / 32768.0f) - mean * mean;
        sh_mean = mean;
        sh_rstd = rsqrtf(var + 1e-5f);
    }
    __syncthreads();
    float mean = sh_mean, rstd = sh_rstd;

    #pragma unroll 4
    for (int i = tid; i < 8192; i += 256) {
        int c = grp * 8 + (i >> 10);
        float sc = rstd * w[c];
        float shf = b[c] - mean * sc;
        float4 t = reinterpret_cast<const float4*>(xp)[i];
        t.x = t.x * sc + shf; t.y = t.y * sc + shf;
        t.z = t.z * sc + shf; t.w = t.w * sc + shf;
        reinterpret_cast<float4*>(op)[i] = t;
    }
}

// ===========================================================================
// Staging helpers (global -> regs -> smem), layouts identical to round-1.
// ===========================================================================
template <bool A_T, int LDA>
__device__ __forceinline__ void stageA(float4 (&pa)[4], const float* __restrict__ A,
                                       int m0, int k0, int tid) {
    if constexpr (A_T) {
        int m = tid >> 3, kq = tid & 7;
        #pragma unroll
        for (int it = 0; it < 4; ++it)
            pa[it] = *reinterpret_cast<const float4*>(&A[(size_t)(m0 + m + 32 * it) * LDA + k0 + kq * 4]);
    } else {
        int kk = tid >> 5, m4 = tid & 31;
        #pragma unroll
        for (int it = 0; it < 4; ++it)
            pa[it] = *reinterpret_cast<const float4*>(&A[(size_t)(k0 + kk + 8 * it) * LDA + m0 + m4 * 4]);
    }
}
template <bool A_T>
__device__ __forceinline__ void commitA(float (*As)[AS_W], const float4 (&pa)[4], int tid) {
    if constexpr (A_T) {
        int m = tid >> 3, kq = tid & 7;
        #pragma unroll
        for (int it = 0; it < 4; ++it) {
            As[kq * 4 + 0][m + 32 * it] = pa[it].x;
            As[kq * 4 + 1][m + 32 * it] = pa[it].y;
            As[kq * 4 + 2][m + 32 * it] = pa[it].z;
            As[kq * 4 + 3][m + 32 * it] = pa[it].w;
        }
    } else {
        int kk = tid >> 5, m4 = tid & 31;
        #pragma unroll
        for (int it = 0; it < 4; ++it)
            *reinterpret_cast<float4*>(&As[kk + 8 * it][m4 * 4]) = pa[it];
    }
}
template <bool B_T, int LDB>
__device__ __forceinline__ void stageB(float4 (&pb)[2], const float* __restrict__ B,
                                       int n0, int k0, int tid) {
    if constexpr (B_T) {
        int n = tid >> 3, kq = tid & 7;
        #pragma unroll
        for (int it = 0; it < 2; ++it)
            pb[it] = *reinterpret_cast<const float4*>(&B[(size_t)(n0 + n + 32 * it) * LDB + k0 + kq * 4]);
    } else {
        int kk = tid >> 4, n4 = tid & 15;
        #pragma unroll
        for (int it = 0; it < 2; ++it)
            pb[it] = *reinterpret_cast<const float4*>(&B[(size_t)(k0 + kk + 16 * it) * LDB + n0 + n4 * 4]);
    }
}
template <bool B_T>
__device__ __forceinline__ void commitB(float (*Bs)[BS_W], const float4 (&pb)[2], int tid) {
    if constexpr (B_T) {
        int n = tid >> 3, kq = tid & 7;
        #pragma unroll
        for (int it = 0; it < 2; ++it) {
            Bs[kq * 4 + 0][n + 32 * it] = pb[it].x;
            Bs[kq * 4 + 1][n + 32 * it] = pb[it].y;
            Bs[kq * 4 + 2][n + 32 * it] = pb[it].z;
            Bs[kq * 4 + 3][n + 32 * it] = pb[it].w;
        }
    } else {
        int kk = tid >> 4, n4 = tid & 15;
        #pragma unroll
        for (int it = 0; it < 2; ++it)
            *reinterpret_cast<float4*>(&Bs[kk + 16 * it][n4 * 4]) = pb[it];
    }
}

// Inner compute: 32 k-steps of row-pair FFMA2 (bitwise == scalar fp32)
__device__ __forceinline__ void compute_tile(const float (*As)[AS_W], const float (*Bs)[BS_W],
                                             unsigned long long (&acc2)[4][4],
                                             int tr, int tc) {
    #pragma unroll
    for (int kk = 0; kk < 32; ++kk) {
        ulonglong2 ua = *reinterpret_cast<const ulonglong2*>(&As[kk][tr * 8]);
        ulonglong2 ub = *reinterpret_cast<const ulonglong2*>(&As[kk][tr * 8 + 4]);
        float4 b0 = *reinterpret_cast<const float4*>(&Bs[kk][tc * 4]);
        unsigned long long bd[4];
        asm("mov.b64 %0, {%1, %1};" : "=l"(bd[0]) : "f"(b0.x));
        asm("mov.b64 %0, {%1, %1};" : "=l"(bd[1]) : "f"(b0.y));
        asm("mov.b64 %0, {%1, %1};" : "=l"(bd[2]) : "f"(b0.z));
        asm("mov.b64 %0, {%1, %1};" : "=l"(bd[3]) : "f"(b0.w));
        #pragma unroll
        for (int j = 0; j < 4; j++) {
            asm("fma.rn.f32x2 %0, %1, %2, %0;" : "+l"(acc2[0][j]) : "l"(ua.x), "l"(bd[j]));
            asm("fma.rn.f32x2 %0, %1, %2, %0;" : "+l"(acc2[1][j]) : "l"(ua.y), "l"(bd[j]));
            asm("fma.rn.f32x2 %0, %1, %2, %0;" : "+l"(acc2[2][j]) : "l"(ub.x), "l"(bd[j]));
            asm("fma.rn.f32x2 %0, %1, %2, %0;" : "+l"(acc2[3][j]) : "l"(ub.y), "l"(bd[j]));
        }
    }
}

// ===========================================================================
// Unified FFMA2 GEMM. Double-buffered smem with COMPILE-TIME phase unrolling
// (one barrier per k-tile, commits overlap laggards' compute). AV uses the
// transposed-V layout so its A-commit is the conflict-free STS.128 path.
// ===========================================================================
#define OP_QKV  0
#define OP_S    1
#define OP_AV   2
#define OP_PROJ 3

template <int OP>
__global__ void __launch_bounds__(256) gemm2_kernel(const float* __restrict__ extA,
                                                    const float* __restrict__ bias,
                                                    const float* __restrict__ resid,
                                                    float* __restrict__ extOut) {
    constexpr int BM = 128, BN = 64, BK = 32;
    constexpr int K   = (OP == OP_AV) ? 4096 : 256;
    constexpr bool A_T = (OP == OP_QKV || OP == OP_PROJ);   // AV now k-major (vT)
    constexpr bool B_T = (OP == OP_AV);
    constexpr int LDA = (OP == OP_QKV || OP == OP_PROJ) ? 256 : ((OP == OP_AV) ? 256 : 4096);
    constexpr int LDB = 4096;

    extern __shared__ float smem[];
    float (*As0)[AS_W] = reinterpret_cast<float(*)[AS_W]>(smem);
    float (*As1)[AS_W] = reinterpret_cast<float(*)[AS_W]>(smem + AS_TILE);
    float (*Bs0)[BS_W] = reinterpret_cast<float(*)[BS_W]>(smem + 2 * AS_TILE);
    float (*Bs1)[BS_W] = reinterpret_cast<float(*)[BS_W]>(smem + 2 * AS_TILE + BS_TILE);

    size_t bz = blockIdx.z;
    const float* A;
    const float* B;
    if constexpr (OP == OP_QKV)      { A = extA;               B = g_xn + bz * STR_CN; }
    else if constexpr (OP == OP_S)   { A = g_q  + bz * STR_CN; B = g_k  + bz * STR_CN; }
    else if constexpr (OP == OP_AV)  { A = g_vT + bz * STR_CN; B = g_S  + bz * STR_NN; }
    else                             { A = extA;               B = g_o  + bz * STR_CN; }

    int m0 = blockIdx.y * BM;
    int n0 = blockIdx.x * BN;
    int tid = threadIdx.x;
    int tr = tid >> 4;
    int tc = tid & 15;

    unsigned long long acc2[4][4];
    #pragma unroll
    for (int i = 0; i < 4; i++)
        #pragma unroll
        for (int j = 0; j < 4; j++) acc2[i][j] = 0ULL;

    // Prologue: tile 0 -> buf0
    {
        float4 pa[4]; float4 pb[2];
        stageA<A_T, LDA>(pa, A, m0, 0, tid);
        stageB<B_T, LDB>(pb, B, n0, 0, tid);
        commitA<A_T>(As0, pa, tid);
        commitB<B_T>(Bs0, pb, tid);
    }
    __syncthreads();

    // Main loop, unrolled by 2 tiles (K % 64 == 0): compile-time buffers.
    #pragma unroll 1
    for (int k0 = 0; k0 < K; k0 += 2 * BK) {
        // phase 0: compute buf0; stage+commit tile(k0+BK) -> buf1 (always valid)
        {
            float4 pa[4]; float4 pb[2];
            stageA<A_T, LDA>(pa, A, m0, k0 + BK, tid);
            stageB<B_T, LDB>(pb, B, n0, k0 + BK, tid);
            compute_tile(As0, Bs0, acc2, tr, tc);
            commitA<A_T>(As1, pa, tid);
            commitB<B_T>(Bs1, pb, tid);
            __syncthreads();
        }
        // phase 1: compute buf1; stage+commit tile(k0+2BK) -> buf0 (if any)
        {
            float4 pa[4]; float4 pb[2];
            bool hn = (k0 + 2 * BK) < K;
            if (hn) {
                stageA<A_T, LDA>(pa, A, m0, k0 + 2 * BK, tid);
                stageB<B_T, LDB>(pb, B, n0, k0 + 2 * BK, tid);
            }
            compute_tile(As1, Bs1, acc2, tr, tc);
            if (hn) {
                commitA<A_T>(As0, pa, tid);
                commitB<B_T>(Bs0, pb, tid);
                __syncthreads();
            }
        }
    }

    // Unpack packed accumulators into the round-1 acc[8][4] shape
    float acc[8][4];
    #pragma unroll
    for (int ip = 0; ip < 4; ip++)
        #pragma unroll
        for (int j = 0; j < 4; j++)
            asm("mov.b64 {%0, %1}, %2;"
                : "=f"(acc[2 * ip][j]), "=f"(acc[2 * ip + 1][j]) : "l"(acc2[ip][j]));

    // ---- proven epilogues ----
    int nbase = n0 + tc * 4;
    if constexpr (OP == OP_QKV) {
        int sec = m0 >> 8;                 // 0=q, 1=k, 2..: v
        int cbase = (m0 & 255) + tr * 8;
        float vals[8][4];
        #pragma unroll
        for (int i = 0; i < 8; i++) {
            float bv = bias[m0 + tr * 8 + i];
            #pragma unroll
            for (int j = 0; j < 4; j++) {
                float v = acc[i][j] + bv;
                if (sec == 0) v *= 0.0625f;     // q pre-scaled by d^-0.5
                vals[i][j] = v;
            }
        }
        if (sec < 2) {
            // q/k: channel-major [c][i] store (round-1 pattern)
            float* d = ((sec == 0) ? g_q : g_k) + bz * STR_CN;
            #pragma unroll
            for (int i = 0; i < 8; i++) {
                size_t off = (size_t)(cbase + i) * NN + nbase;
                *reinterpret_cast<float4*>(&d[off]) =
                    make_float4(vals[i][0], vals[i][1], vals[i][2], vals[i][3]);
            }
        } else {
            // v: TRANSPOSED store [j][c] (R11-proven pattern)
            float* dT = g_vT + bz * STR_CN;
            #pragma unroll
            for (int j = 0; j < 4; j++) {
                float4 r0 = make_float4(vals[0][j], vals[1][j], vals[2][j], vals[3][j]);
                float4 r1 = make_float4(vals[4][j], vals[5][j], vals[6][j], vals[7][j]);
                size_t off = (size_t)(nbase + j) * NC + cbase;
                *reinterpret_cast<float4*>(&dT[off])     = r0;
                *reinterpret_cast<float4*>(&dT[off + 4]) = r1;
            }
        }
    } else if constexpr (OP == OP_S) {
        #pragma unroll
        for (int i = 0; i < 8; i++) {
            int m = m0 + tr * 8 + i;
            *reinterpret_cast<float4*>(&g_S[bz * STR_NN + (size_t)m * NN + nbase]) =
                make_float4(acc[i][0], acc[i][1], acc[i][2], acc[i][3]);
        }
    } else if constexpr (OP == OP_AV) {
        #pragma unroll
        for (int i = 0; i < 8; i++) {
            int m = m0 + tr * 8 + i;
            *reinterpret_cast<float4*>(&g_o[bz * STR_CN + (size_t)m * NN + nbase]) =
                make_float4(acc[i][0], acc[i][1], acc[i][2], acc[i][3]);
        }
    } else {  // OP_PROJ
        #pragma unroll
        for (int i = 0; i < 8; i++) {
            int m = m0 + tr * 8 + i;
            float bv = bias[m];
            size_t off = bz * STR_CN + (size_t)m * NN + nbase;
            float4 xr = *reinterpret_cast<const float4*>(&resid[off]);
            float4 r = make_float4(acc[i][0] + bv + xr.x, acc[i][1] + bv + xr.y,
                                   acc[i][2] + bv + xr.z, acc[i][3] + bv + xr.w);
            *reinterpret_cast<float4*>(&extOut[off]) = r;
        }
    }
}

// ===========================================================================
// Softmax (round-1 proven), in place on g_S
// ===========================================================================
__global__ void __launch_bounds__(256) softmax_kernel() {
    size_t row = blockIdx.x;
    float* p = g_S + row * NN;
    int tid = threadIdx.x;
    int lane = tid & 31, wid = tid >> 5;
    __shared__ float red[8];
    __shared__ float sh_bcast;

    float4 v[4];
    float mx = -INFINITY;
    #pragma unroll
    for (int i = 0; i < 4; i++) {
        v[i] = reinterpret_cast<float4*>(p)[tid + i * 256];
        mx = fmaxf(mx, fmaxf(fmaxf(v[i].x, v[i].y), fmaxf(v[i].z, v[i].w)));
    }
    #pragma unroll
    for (int o = 16; o; o >>= 1) mx = fmaxf(mx, __shfl_xor_sync(0xffffffffu, mx, o));
    if (lane == 0) red[wid] = mx;
    __syncthreads();
    if (tid == 0) {
        float m = red[0];
        #pragma unroll
        for (int i = 1; i < 8; i++) m = fmaxf(m, red[i]);
        sh_bcast = m;
    }
    __syncthreads();
    mx = sh_bcast;
    __syncthreads();

    float sum = 0.f;
    #pragma unroll
    for (int i = 0; i < 4; i++) {
        v[i].x = __expf(v[i].x - mx); v[i].y = __expf(v[i].y - mx);
        v[i].z = __expf(v[i].z - mx); v[i].w = __expf(v[i].w - mx);
        sum += v[i].x + v[i].y + v[i].z + v[i].w;
    }
    #pragma unroll
    for (int o = 16; o; o >>= 1) sum += __shfl_xor_sync(0xffffffffu, sum, o);
    if (lane == 0) red[wid] = sum;
    __syncthreads();
    if (tid == 0) {
        float s = 0.f;
        #pragma unroll
        for (int i = 0; i < 8; i++) s += red[i];
        sh_bcast = 1.0f / s;
    }
    __syncthreads();
    float inv = sh_bcast;

    #pragma unroll
    for (int i = 0; i < 4; i++) {
        v[i].x *= inv; v[i].y *= inv; v[i].z *= inv; v[i].w *= inv;
        reinterpret_cast<float4*>(p)[tid + i * 256] = v[i];
    }
}

// ===========================================================================
extern "C" void kernel_launch(void* const* d_in, const int* in_sizes, int n_in,
                              void* d_out, int out_size) {
    const float* x      = (const float*)d_in[0];
    const float* norm_w = (const float*)d_in[1];
    const float* norm_b = (const float*)d_in[2];
    const float* qkv_w  = (const float*)d_in[3];
    const float* qkv_b  = (const float*)d_in[4];
    const float* proj_w = (const float*)d_in[5];
    const float* proj_b = (const float*)d_in[6];
    float* out = (float*)d_out;

    cudaFuncSetAttribute(gemm2_kernel<OP_QKV>,  cudaFuncAttributeMaxDynamicSharedMemorySize, GEMM_SMEM);
    cudaFuncSetAttribute(gemm2_kernel<OP_S>,    cudaFuncAttributeMaxDynamicSharedMemorySize, GEMM_SMEM);
    cudaFuncSetAttribute(gemm2_kernel<OP_AV>,   cudaFuncAttributeMaxDynamicSharedMemorySize, GEMM_SMEM);
    cudaFuncSetAttribute(gemm2_kernel<OP_PROJ>, cudaFuncAttributeMaxDynamicSharedMemorySize, GEMM_SMEM);

    // 1. GroupNorm -> g_xn
    gn_kernel<<<NB * NGRP, 256>>>(x, norm_w, norm_b);

    // 2. QKV GEMM (f32x2) -> g_q (scaled), g_k, g_vT
    gemm2_kernel<OP_QKV><<<dim3(NN / 64, 768 / 128, NB), 256, GEMM_SMEM>>>(qkv_w, qkv_b, nullptr, nullptr);

    // 3. S = Q^T K (f32x2)
    gemm2_kernel<OP_S><<<dim3(NN / 64, NN / 128, NB), 256, GEMM_SMEM>>>(nullptr, nullptr, nullptr, nullptr);

    // 4. softmax (fp32, proven)
    softmax_kernel<<<NB * NN, 256>>>();

    // 5. O = V P^T (f32x2, vT k-major A operand)
    gemm2_kernel<OP_AV><<<dim3(NN / 64, NC / 128, NB), 256, GEMM_SMEM>>>(nullptr, nullptr, nullptr, nullptr);

    // 6. proj + bias + residual (f32x2)
    gemm2_kernel<OP_PROJ><<<dim3(NN / 64, NC / 128, NB), 256, GEMM_SMEM>>>(proj_w, proj_b, x, out);
}

// round 17
// speedup vs baseline: 1.4072x; 1.0371x over previous
#include <cuda_runtime.h>
#include <cstdint>
#include <math.h>

// Problem constants: B=4, C=256, H=W=64 -> N=4096, num_heads=1, d=256
#define NB    4
#define NC    256
#define NN    4096
#define NGRP  32

static __device__ float g_xn[NB * NC * NN];
static __device__ float g_q [NB * NC * NN];   // [b][c][i], q pre-scaled by d^-0.5
static __device__ float g_k [NB * NC * NN];
static __device__ float g_vT[NB * NN * NC];   // [b][j][c]  (transposed V)
static __device__ float g_o [NB * NC * NN];
static __device__ float g_S [(size_t)NB * NN * NN];   // 256 MB scores / probs

static constexpr size_t STR_CN = (size_t)NC * NN;     // 1048576
static constexpr size_t STR_NN = (size_t)NN * NN;     // 16777216

// smem geometry (double-buffered)
static constexpr int AS_W = 132;
static constexpr int BS_W = 68;
static constexpr int AS_TILE = 32 * AS_W;
static constexpr int BS_TILE = 32 * BS_W;
static constexpr int GEMM_SMEM = (2 * AS_TILE + 2 * BS_TILE) * 4;   // 51200 B

// ===========================================================================
// cp.async helpers (base PTX, sm_80+)
// ===========================================================================
__device__ __forceinline__ void cpa16(uint32_t saddr, const float* g) {
    asm volatile("cp.async.cg.shared.global [%0], [%1], 16;" :: "r"(saddr), "l"(g));
}
#define CPA_COMMIT() asm volatile("cp.async.commit_group;" ::: "memory")
#define CPA_WAIT0()  asm volatile("cp.async.wait_group 0;" ::: "memory")

// ===========================================================================
// GroupNorm (round-1 proven)
// ===========================================================================
__global__ void __launch_bounds__(256) gn_kernel(const float* __restrict__ x,
                                                 const float* __restrict__ w,
                                                 const float* __restrict__ b) {
    int batch = blockIdx.x >> 5;
    int grp   = blockIdx.x & 31;
    const float* xp = x    + ((size_t)batch * NC + grp * 8) * NN;
    float*       op = g_xn + ((size_t)batch * NC + grp * 8) * NN;
    int tid = threadIdx.x;

    float s = 0.f, s2 = 0.f;
    #pragma unroll 4
    for (int i = tid; i < 8192; i += 256) {
        float4 t = reinterpret_cast<const float4*>(xp)[i];
        s  += t.x + t.y + t.z + t.w;
        s2 += t.x * t.x + t.y * t.y + t.z * t.z + t.w * t.w;
    }
    __shared__ float rs[8], rs2[8];
    __shared__ float sh_mean, sh_rstd;
    int lane = tid & 31, wid = tid >> 5;
    #pragma unroll
    for (int o = 16; o; o >>= 1) {
        s  += __shfl_xor_sync(0xffffffffu, s,  o);
        s2 += __shfl_xor_sync(0xffffffffu, s2, o);
    }
    if (lane == 0) { rs[wid] = s; rs2[wid] = s2; }
    __syncthreads();
    if (tid == 0) {
        float ts = 0.f, ts2 = 0.f;
        #pragma unroll
        for (int i = 0; i < 8; i++) { ts += rs[i]; ts2 += rs2[i]; }
        float mean = ts * (1.0f / 32768.0f);
        float var  = ts2 * (1.0f / 32768.0f) - mean * mean;
        sh_mean = mean;
        sh_rstd = rsqrtf(var + 1e-5f);
    }
    __syncthreads();
    float mean = sh_mean, rstd = sh_rstd;

    #pragma unroll 4
    for (int i = tid; i < 8192; i += 256) {
        int c = grp * 8 + (i >> 10);
        float sc = rstd * w[c];
        float shf = b[c] - mean * sc;
        float4 t = reinterpret_cast<const float4*>(xp)[i];
        t.x = t.x * sc + shf; t.y = t.y * sc + shf;
        t.z = t.z * sc + shf; t.w = t.w * sc + shf;
        reinterpret_cast<float4*>(op)[i] = t;
    }
}

// ===========================================================================
// Staging helpers (register path, for transposed operands only)
// ===========================================================================
template <int LDA>
__device__ __forceinline__ void stageA_T(float4 (&pa)[4], const float* __restrict__ A,
                                         int m0, int k0, int tid) {
    int m = tid >> 3, kq = tid & 7;
    #pragma unroll
    for (int it = 0; it < 4; ++it)
        pa[it] = *reinterpret_cast<const float4*>(&A[(size_t)(m0 + m + 32 * it) * LDA + k0 + kq * 4]);
}
__device__ __forceinline__ void commitA_T(float (*As)[AS_W], const float4 (&pa)[4], int tid) {
    int m = tid >> 3, kq = tid & 7;
    #pragma unroll
    for (int it = 0; it < 4; ++it) {
        As[kq * 4 + 0][m + 32 * it] = pa[it].x;
        As[kq * 4 + 1][m + 32 * it] = pa[it].y;
        As[kq * 4 + 2][m + 32 * it] = pa[it].z;
        As[kq * 4 + 3][m + 32 * it] = pa[it].w;
    }
}
template <int LDB>
__device__ __forceinline__ void stageB_T(float4 (&pb)[2], const float* __restrict__ B,
                                         int n0, int k0, int tid) {
    int n = tid >> 3, kq = tid & 7;
    #pragma unroll
    for (int it = 0; it < 2; ++it)
        pb[it] = *reinterpret_cast<const float4*>(&B[(size_t)(n0 + n + 32 * it) * LDB + k0 + kq * 4]);
}
__device__ __forceinline__ void commitB_T(float (*Bs)[BS_W], const float4 (&pb)[2], int tid) {
    int n = tid >> 3, kq = tid & 7;
    #pragma unroll
    for (int it = 0; it < 2; ++it) {
        Bs[kq * 4 + 0][n + 32 * it] = pb[it].x;
        Bs[kq * 4 + 1][n + 32 * it] = pb[it].y;
        Bs[kq * 4 + 2][n + 32 * it] = pb[it].z;
        Bs[kq * 4 + 3][n + 32 * it] = pb[it].w;
    }
}

// cp.async direct copies (non-transposed operands)
template <int LDA>
__device__ __forceinline__ void cpaA(uint32_t asbase, const float* __restrict__ A,
                                     int m0, int k0, int tid) {
    int kk = tid >> 5, m4 = tid & 31;
    #pragma unroll
    for (int it = 0; it < 4; ++it)
        cpa16(asbase + (uint32_t)(((kk + 8 * it) * AS_W + m4 * 4) * 4),
              &A[(size_t)(k0 + kk + 8 * it) * LDA + m0 + m4 * 4]);
}
template <int LDB>
__device__ __forceinline__ void cpaB(uint32_t bsbase, const float* __restrict__ B,
                                     int n0, int k0, int tid) {
    int kk = tid >> 4, n4 = tid & 15;
    #pragma unroll
    for (int it = 0; it < 2; ++it)
        cpa16(bsbase + (uint32_t)(((kk + 16 * it) * BS_W + n4 * 4) * 4),
              &B[(size_t)(k0 + kk + 16 * it) * LDB + n0 + n4 * 4]);
}

// Inner compute: 32 k-steps of row-pair FFMA2 (bitwise == scalar fp32)
__device__ __forceinline__ void compute_tile(const float (*As)[AS_W], const float (*Bs)[BS_W],
                                             unsigned long long (&acc2)[4][4],
                                             int tr, int tc) {
    #pragma unroll
    for (int kk = 0; kk < 32; ++kk) {
        ulonglong2 ua = *reinterpret_cast<const ulonglong2*>(&As[kk][tr * 8]);
        ulonglong2 ub = *reinterpret_cast<const ulonglong2*>(&As[kk][tr * 8 + 4]);
        float4 b0 = *reinterpret_cast<const float4*>(&Bs[kk][tc * 4]);
        unsigned long long bd[4];
        asm("mov.b64 %0, {%1, %1};" : "=l"(bd[0]) : "f"(b0.x));
        asm("mov.b64 %0, {%1, %1};" : "=l"(bd[1]) : "f"(b0.y));
        asm("mov.b64 %0, {%1, %1};" : "=l"(bd[2]) : "f"(b0.z));
        asm("mov.b64 %0, {%1, %1};" : "=l"(bd[3]) : "f"(b0.w));
        #pragma unroll
        for (int j = 0; j < 4; j++) {
            asm("fma.rn.f32x2 %0, %1, %2, %0;" : "+l"(acc2[0][j]) : "l"(ua.x), "l"(bd[j]));
            asm("fma.rn.f32x2 %0, %1, %2, %0;" : "+l"(acc2[1][j]) : "l"(ua.y), "l"(bd[j]));
            asm("fma.rn.f32x2 %0, %1, %2, %0;" : "+l"(acc2[2][j]) : "l"(ub.x), "l"(bd[j]));
            asm("fma.rn.f32x2 %0, %1, %2, %0;" : "+l"(acc2[3][j]) : "l"(ub.y), "l"(bd[j]));
        }
    }
}

// ===========================================================================
// Unified FFMA2 GEMM. Double-buffered (compile-time phases, 1 barrier/tile).
// Non-transposed operands move via cp.async (no staging regs, no STS phase);
// transposed operands (weights A for QKV/PROJ, S-rows B for AV) keep the
// register-staged path. Math identical to scalar fp32 (bitwise).
// ===========================================================================
#define OP_QKV  0
#define OP_S    1
#define OP_AV   2
#define OP_PROJ 3

template <int OP>
__global__ void __launch_bounds__(256) gemm2_kernel(const float* __restrict__ extA,
                                                    const float* __restrict__ bias,
                                                    const float* __restrict__ resid,
                                                    float* __restrict__ extOut) {
    constexpr int BM = 128, BN = 64, BK = 32;
    constexpr int K   = (OP == OP_AV) ? 4096 : 256;
    constexpr bool A_T = (OP == OP_QKV || OP == OP_PROJ);   // A is [M][K] (weights)
    constexpr bool B_T = (OP == OP_AV);                      // B is [N][K] (S rows)
    constexpr bool CPA_A = !A_T;
    constexpr bool CPA_B = !B_T;
    constexpr int LDA = (OP == OP_QKV || OP == OP_PROJ) ? 256 : ((OP == OP_AV) ? 256 : 4096);
    constexpr int LDB = 4096;

    extern __shared__ float smem[];
    float (*As0)[AS_W] = reinterpret_cast<float(*)[AS_W]>(smem);
    float (*As1)[AS_W] = reinterpret_cast<float(*)[AS_W]>(smem + AS_TILE);
    float (*Bs0)[BS_W] = reinterpret_cast<float(*)[BS_W]>(smem + 2 * AS_TILE);
    float (*Bs1)[BS_W] = reinterpret_cast<float(*)[BS_W]>(smem + 2 * AS_TILE + BS_TILE);
    uint32_t sb  = (uint32_t)__cvta_generic_to_shared(smem);
    uint32_t uAs0 = sb, uAs1 = sb + AS_TILE * 4;
    uint32_t uBs0 = sb + 2 * AS_TILE * 4, uBs1 = uBs0 + BS_TILE * 4;

    size_t bz = blockIdx.z;
    const float* A;
    const float* B;
    if constexpr (OP == OP_QKV)      { A = extA;               B = g_xn + bz * STR_CN; }
    else if constexpr (OP == OP_S)   { A = g_q  + bz * STR_CN; B = g_k  + bz * STR_CN; }
    else if constexpr (OP == OP_AV)  { A = g_vT + bz * STR_CN; B = g_S  + bz * STR_NN; }
    else                             { A = extA;               B = g_o  + bz * STR_CN; }

    int m0 = blockIdx.y * BM;
    int n0 = blockIdx.x * BN;
    int tid = threadIdx.x;
    int tr = tid >> 4;
    int tc = tid & 15;

    unsigned long long acc2[4][4];
    #pragma unroll
    for (int i = 0; i < 4; i++)
        #pragma unroll
        for (int j = 0; j < 4; j++) acc2[i][j] = 0ULL;

    // Prologue: tile 0 -> buf0
    {
        if constexpr (CPA_A) cpaA<LDA>(uAs0, A, m0, 0, tid);
        if constexpr (CPA_B) cpaB<LDB>(uBs0, B, n0, 0, tid);
        if constexpr (CPA_A || CPA_B) CPA_COMMIT();
        if constexpr (!CPA_A) { float4 pa[4]; stageA_T<LDA>(pa, A, m0, 0, tid); commitA_T(As0, pa, tid); }
        if constexpr (!CPA_B) { float4 pb[2]; stageB_T<LDB>(pb, B, n0, 0, tid); commitB_T(Bs0, pb, tid); }
        if constexpr (CPA_A || CPA_B) CPA_WAIT0();
    }
    __syncthreads();

    // Main loop, unrolled by 2 tiles (K % 64 == 0): compile-time buffers.
    #pragma unroll 1
    for (int k0 = 0; k0 < K; k0 += 2 * BK) {
        // phase 0: compute buf0; fill buf1 with tile(k0+BK) (always valid)
        {
            if constexpr (CPA_A) cpaA<LDA>(uAs1, A, m0, k0 + BK, tid);
            if constexpr (CPA_B) cpaB<LDB>(uBs1, B, n0, k0 + BK, tid);
            if constexpr (CPA_A || CPA_B) CPA_COMMIT();
            float4 pa[4]; float4 pb[2];
            if constexpr (!CPA_A) stageA_T<LDA>(pa, A, m0, k0 + BK, tid);
            if constexpr (!CPA_B) stageB_T<LDB>(pb, B, n0, k0 + BK, tid);
            compute_tile(As0, Bs0, acc2, tr, tc);
            if constexpr (!CPA_A) commitA_T(As1, pa, tid);
            if constexpr (!CPA_B) commitB_T(Bs1, pb, tid);
            if constexpr (CPA_A || CPA_B) CPA_WAIT0();
            __syncthreads();
        }
        // phase 1: compute buf1; fill buf0 with tile(k0+2BK) (if any)
        {
            bool hn = (k0 + 2 * BK) < K;
            if (hn) {
                if constexpr (CPA_A) cpaA<LDA>(uAs0, A, m0, k0 + 2 * BK, tid);
                if constexpr (CPA_B) cpaB<LDB>(uBs0, B, n0, k0 + 2 * BK, tid);
                if constexpr (CPA_A || CPA_B) CPA_COMMIT();
            }
            float4 pa[4]; float4 pb[2];
            if (hn) {
                if constexpr (!CPA_A) stageA_T<LDA>(pa, A, m0, k0 + 2 * BK, tid);
                if constexpr (!CPA_B) stageB_T<LDB>(pb, B, n0, k0 + 2 * BK, tid);
            }
            compute_tile(As1, Bs1, acc2, tr, tc);
            if (hn) {
                if constexpr (!CPA_A) commitA_T(As0, pa, tid);
                if constexpr (!CPA_B) commitB_T(Bs0, pb, tid);
                if constexpr (CPA_A || CPA_B) CPA_WAIT0();
                __syncthreads();
            }
        }
    }

    // Unpack packed accumulators into acc[8][4]
    float acc[8][4];
    #pragma unroll
    for (int ip = 0; ip < 4; ip++)
        #pragma unroll
        for (int j = 0; j < 4; j++)
            asm("mov.b64 {%0, %1}, %2;"
                : "=f"(acc[2 * ip][j]), "=f"(acc[2 * ip + 1][j]) : "l"(acc2[ip][j]));

    // ---- proven epilogues (R16) ----
    int nbase = n0 + tc * 4;
    if constexpr (OP == OP_QKV) {
        int sec = m0 >> 8;
        int cbase = (m0 & 255) + tr * 8;
        float vals[8][4];
        #pragma unroll
        for (int i = 0; i < 8; i++) {
            float bv = bias[m0 + tr * 8 + i];
            #pragma unroll
            for (int j = 0; j < 4; j++) {
                float v = acc[i][j] + bv;
                if (sec == 0) v *= 0.0625f;     // q pre-scaled by d^-0.5
                vals[i][j] = v;
            }
        }
        if (sec < 2) {
            float* d = ((sec == 0) ? g_q : g_k) + bz * STR_CN;
            #pragma unroll
            for (int i = 0; i < 8; i++) {
                size_t off = (size_t)(cbase + i) * NN + nbase;
                *reinterpret_cast<float4*>(&d[off]) =
                    make_float4(vals[i][0], vals[i][1], vals[i][2], vals[i][3]);
            }
        } else {
            float* dT = g_vT + bz * STR_CN;
            #pragma unroll
            for (int j = 0; j < 4; j++) {
                float4 r0 = make_float4(vals[0][j], vals[1][j], vals[2][j], vals[3][j]);
                float4 r1 = make_float4(vals[4][j], vals[5][j], vals[6][j], vals[7][j]);
                size_t off = (size_t)(nbase + j) * NC + cbase;
                *reinterpret_cast<float4*>(&dT[off])     = r0;
                *reinterpret_cast<float4*>(&dT[off + 4]) = r1;
            }
        }
    } else if constexpr (OP == OP_S) {
        #pragma unroll
        for (int i = 0; i < 8; i++) {
            int m = m0 + tr * 8 + i;
            *reinterpret_cast<float4*>(&g_S[bz * STR_NN + (size_t)m * NN + nbase]) =
                make_float4(acc[i][0], acc[i][1], acc[i][2], acc[i][3]);
        }
    } else if constexpr (OP == OP_AV) {
        #pragma unroll
        for (int i = 0; i < 8; i++) {
            int m = m0 + tr * 8 + i;
            *reinterpret_cast<float4*>(&g_o[bz * STR_CN + (size_t)m * NN + nbase]) =
                make_float4(acc[i][0], acc[i][1], acc[i][2], acc[i][3]);
        }
    } else {  // OP_PROJ
        #pragma unroll
        for (int i = 0; i < 8; i++) {
            int m = m0 + tr * 8 + i;
            float bv = bias[m];
            size_t off = bz * STR_CN + (size_t)m * NN + nbase;
            float4 xr = *reinterpret_cast<const float4*>(&resid[off]);
            float4 r = make_float4(acc[i][0] + bv + xr.x, acc[i][1] + bv + xr.y,
                                   acc[i][2] + bv + xr.z, acc[i][3] + bv + xr.w);
            *reinterpret_cast<float4*>(&extOut[off]) = r;
        }
    }
}

// ===========================================================================
// Softmax (round-1 proven), in place on g_S
// ===========================================================================
__global__ void __launch_bounds__(256) softmax_kernel() {
    size_t row = blockIdx.x;
    float* p = g_S + row * NN;
    int tid = threadIdx.x;
    int lane = tid & 31, wid = tid >> 5;
    __shared__ float red[8];
    __shared__ float sh_bcast;

    float4 v[4];
    float mx = -INFINITY;
    #pragma unroll
    for (int i = 0; i < 4; i++) {
        v[i] = reinterpret_cast<float4*>(p)[tid + i * 256];
        mx = fmaxf(mx, fmaxf(fmaxf(v[i].x, v[i].y), fmaxf(v[i].z, v[i].w)));
    }
    #pragma unroll
    for (int o = 16; o; o >>= 1) mx = fmaxf(mx, __shfl_xor_sync(0xffffffffu, mx, o));
    if (lane == 0) red[wid] = mx;
    __syncthreads();
    if (tid == 0) {
        float m = red[0];
        #pragma unroll
        for (int i = 1; i < 8; i++) m = fmaxf(m, red[i]);
        sh_bcast = m;
    }
    __syncthreads();
    mx = sh_bcast;
    __syncthreads();

    float sum = 0.f;
    #pragma unroll
    for (int i = 0; i < 4; i++) {
        v[i].x = __expf(v[i].x - mx); v[i].y = __expf(v[i].y - mx);
        v[i].z = __expf(v[i].z - mx); v[i].w = __expf(v[i].w - mx);
        sum += v[i].x + v[i].y + v[i].z + v[i].w;
    }
    #pragma unroll
    for (int o = 16; o; o >>= 1) sum += __shfl_xor_sync(0xffffffffu, sum, o);
    if (lane == 0) red[wid] = sum;
    __syncthreads();
    if (tid == 0) {
        float s = 0.f;
        #pragma unroll
        for (int i = 0; i < 8; i++) s += red[i];
        sh_bcast = 1.0f / s;
    }
    __syncthreads();
    float inv = sh_bcast;

    #pragma unroll
    for (int i = 0; i < 4; i++) {
        v[i].x *= inv; v[i].y *= inv; v[i].z *= inv; v[i].w *= inv;
        reinterpret_cast<float4*>(p)[tid + i * 256] = v[i];
    }
}

// ===========================================================================
extern "C" void kernel_launch(void* const* d_in, const int* in_sizes, int n_in,
                              void* d_out, int out_size) {
    const float* x      = (const float*)d_in[0];
    const float* norm_w = (const float*)d_in[1];
    const float* norm_b = (const float*)d_in[2];
    const float* qkv_w  = (const float*)d_in[3];
    const float* qkv_b  = (const float*)d_in[4];
    const float* proj_w = (const float*)d_in[5];
    const float* proj_b = (const float*)d_in[6];
    float* out = (float*)d_out;

    cudaFuncSetAttribute(gemm2_kernel<OP_QKV>,  cudaFuncAttributeMaxDynamicSharedMemorySize, GEMM_SMEM);
    cudaFuncSetAttribute(gemm2_kernel<OP_S>,    cudaFuncAttributeMaxDynamicSharedMemorySize, GEMM_SMEM);
    cudaFuncSetAttribute(gemm2_kernel<OP_AV>,   cudaFuncAttributeMaxDynamicSharedMemorySize, GEMM_SMEM);
    cudaFuncSetAttribute(gemm2_kernel<OP_PROJ>, cudaFuncAttributeMaxDynamicSharedMemorySize, GEMM_SMEM);

    // 1. GroupNorm -> g_xn
    gn_kernel<<<NB * NGRP, 256>>>(x, norm_w, norm_b);

    // 2. QKV GEMM (f32x2) -> g_q (scaled), g_k, g_vT
    gemm2_kernel<OP_QKV><<<dim3(NN / 64, 768 / 128, NB), 256, GEMM_SMEM>>>(qkv_w, qkv_b, nullptr, nullptr);

    // 3. S = Q^T K (f32x2, both operands via cp.async)
    gemm2_kernel<OP_S><<<dim3(NN / 64, NN / 128, NB), 256, GEMM_SMEM>>>(nullptr, nullptr, nullptr, nullptr);

    // 4. softmax (fp32, proven)
    softmax_kernel<<<NB * NN, 256>>>();

    // 5. O = V P^T (f32x2, A via cp.async)
    gemm2_kernel<OP_AV><<<dim3(NN / 64, NC / 128, NB), 256, GEMM_SMEM>>>(nullptr, nullptr, nullptr, nullptr);

    // 6. proj + bias + residual (f32x2, B via cp.async)
    gemm2_kernel<OP_PROJ><<<dim3(NN / 64, NC / 128, NB), 256, GEMM_SMEM>>>(proj_w, proj_b, x, out);
}